// round 1
// baseline (speedup 1.0000x reference)
#include <cuda_runtime.h>
#include <cstdint>

// FactorizedSpectralConv on GB300.
// B=16, C=64, H=W=128, M0=M1=16. Only 32 kx rows (0..15, 112..127) and
// 16 ky cols of the spectrum matter -> direct small DFTs, no full FFT.
//
// K1 (per (b,t) image): F[h,ky] = sum_w X[h,w] e^{-2pi i ky w/128}  (SMEM)
//                       Xf[kx,ky] = sum_h F[h,ky] e^{-2pi i kx h/128}
//                       scaled by 1/16384 (norm="forward")
// K2 (per mode m):      Y[c,b] = sum_t W[c,t,m] * Xf[t,b,m]   (complex GEMM)
// K3 (per (b,c) image): Z[h,ky] = sum_kx Y[kx,ky] e^{+2pi i kx h/128}  (SMEM)
//                       out[h,w] = Re(Z[h,0]) + 2*sum_{ky=1..15} Re(Z[h,ky] e^{+2pi i ky w/128})

#define PI2_OVER_128 0.04908738521234051935f  // 2*pi/128

// Scratch (device globals; allocation-free rule)
__device__ float2 g_Xf[512 * 64 * 16];  // [mode][t][b], 4 MB
__device__ float2 g_Y [16 * 64 * 512];  // [b][c][mode], 4 MB

// ---------------------------------------------------------------------------
// K1: forward. grid = B*C = 1024 blocks, 128 threads (thread = h row).
// ---------------------------------------------------------------------------
__global__ void __launch_bounds__(128) k_forward(const float* __restrict__ X) {
    __shared__ float4 TWf4[128][8];   // [w][ky-pair] = (cos0,-sin0,cos1,-sin1)
    __shared__ float2 rootF[128];     // e^{-2pi i n/128}
    __shared__ float  Xs[128][17];    // 16-wide w chunk, padded
    __shared__ float2 Fw[16][129];    // [ky][h], padded

    int tid = threadIdx.x;

    // Build twiddle tables
    #pragma unroll
    for (int e = tid; e < 1024; e += 128) {
        int w = e >> 3, k2 = e & 7;
        int n0 = (w * (2 * k2)) & 127;
        int n1 = (w * (2 * k2 + 1)) & 127;
        float s0, c0, s1, c1;
        sincosf(PI2_OVER_128 * (float)n0, &s0, &c0);
        sincosf(PI2_OVER_128 * (float)n1, &s1, &c1);
        TWf4[w][k2] = make_float4(c0, -s0, c1, -s1);
    }
    {
        float s, c;
        sincosf(PI2_OVER_128 * (float)tid, &s, &c);
        rootF[tid] = make_float2(c, -s);
    }

    const float* Xp = X + (size_t)blockIdx.x * 16384;

    // Phase A: row DFT along w for this thread's row h = tid
    float ar[16], ai[16];
    #pragma unroll
    for (int k = 0; k < 16; k++) { ar[k] = 0.f; ai[k] = 0.f; }

    for (int c0 = 0; c0 < 128; c0 += 16) {
        __syncthreads();
        #pragma unroll
        for (int p = 0; p < 16; p++) {
            int i = tid + p * 128;
            int r = i >> 4, w = i & 15;
            Xs[r][w] = Xp[r * 128 + c0 + w];
        }
        __syncthreads();
        #pragma unroll
        for (int w2 = 0; w2 < 16; w2++) {
            float xv = Xs[tid][w2];
            #pragma unroll
            for (int k2 = 0; k2 < 8; k2++) {
                float4 tv = TWf4[c0 + w2][k2];
                ar[2 * k2]     += xv * tv.x;
                ai[2 * k2]     += xv * tv.y;
                ar[2 * k2 + 1] += xv * tv.z;
                ai[2 * k2 + 1] += xv * tv.w;
            }
        }
    }

    // Stash scaled row spectrum into SMEM (norm="forward": 1/(H*W))
    #pragma unroll
    for (int k = 0; k < 16; k++)
        Fw[k][tid] = make_float2(ar[k] * (1.f / 16384.f), ai[k] * (1.f / 16384.f));
    __syncthreads();

    // Phase B: column DFT along h for 32 kept kx. thread -> (ky, 4 kx)
    int ky = tid & 15, kxg = tid >> 4;
    float br[4], bi[4];
    int kxv[4], idx[4];
    #pragma unroll
    for (int j = 0; j < 4; j++) {
        br[j] = bi[j] = 0.f;
        int kxIdx = kxg * 4 + j;
        kxv[j] = (kxIdx < 16) ? kxIdx : (96 + kxIdx);  // 112..127 for bottom block
        idx[j] = 0;
    }
    for (int h = 0; h < 128; h++) {
        float2 f = Fw[ky][h];
        #pragma unroll
        for (int j = 0; j < 4; j++) {
            float2 e = rootF[idx[j]];
            br[j] += f.x * e.x - f.y * e.y;
            bi[j] += f.x * e.y + f.y * e.x;
            idx[j] = (idx[j] + kxv[j]) & 127;
        }
    }

    int b = blockIdx.x >> 6, t = blockIdx.x & 63;
    #pragma unroll
    for (int j = 0; j < 4; j++) {
        int m = (kxg * 4 + j) * 16 + ky;
        g_Xf[(m * 64 + t) * 16 + b] = make_float2(br[j], bi[j]);
    }
}

// ---------------------------------------------------------------------------
// K2: mode mixing. grid = 512 modes, 256 threads. thread -> (4 c, 1 b).
// ---------------------------------------------------------------------------
__global__ void __launch_bounds__(256) k_modes(
    const float* __restrict__ w0r, const float* __restrict__ w0i,
    const float* __restrict__ w1r, const float* __restrict__ w1i) {
    __shared__ float2 Ws[64][65];   // [c][t], padded
    __shared__ float2 Xs[64][17];   // [t][b], padded

    int m = blockIdx.x;
    int kxIdx = m >> 4, ky = m & 15;
    const float* Wr = (kxIdx < 16) ? w0r : w1r;
    const float* Wi = (kxIdx < 16) ? w0i : w1i;
    int kx0 = (kxIdx < 16) ? kxIdx : (kxIdx - 16);
    int woff = kx0 * 16 + ky;
    int tid = threadIdx.x;

    #pragma unroll
    for (int p = 0; p < 16; p++) {
        int i = tid + p * 256;                       // i = c*64 + t
        Ws[i >> 6][i & 63] = make_float2(Wr[i * 256 + woff], Wi[i * 256 + woff]);
    }
    #pragma unroll
    for (int p = 0; p < 4; p++) {
        int i = tid + p * 256;                       // i = t*16 + b
        Xs[i >> 4][i & 15] = g_Xf[m * 1024 + i];
    }
    __syncthreads();

    int b = tid & 15, cq = tid >> 4;
    float yr[4] = {0.f, 0.f, 0.f, 0.f}, yi[4] = {0.f, 0.f, 0.f, 0.f};
    for (int t = 0; t < 64; t++) {
        float2 xv = Xs[t][b];
        #pragma unroll
        for (int j = 0; j < 4; j++) {
            float2 w = Ws[cq * 4 + j][t];
            yr[j] += w.x * xv.x - w.y * xv.y;
            yi[j] += w.x * xv.y + w.y * xv.x;
        }
    }
    #pragma unroll
    for (int j = 0; j < 4; j++) {
        int c = cq * 4 + j;
        g_Y[(size_t)(b * 64 + c) * 512 + m] = make_float2(yr[j], yi[j]);
    }
}

// ---------------------------------------------------------------------------
// K3: inverse. grid = B*C = 1024 blocks, 256 threads.
// ---------------------------------------------------------------------------
__global__ void __launch_bounds__(256) k_inverse(float* __restrict__ out) {
    __shared__ float2 rootI[128];     // e^{+2pi i n/128}
    __shared__ float2 Ys[32][16];     // [kxIdx][ky]
    __shared__ float4 Zs4[128][9];    // [h][ky-pair], row pitch 9 (8 used)

    int tid = threadIdx.x;
    if (tid < 128) {
        float s, c;
        sincosf(PI2_OVER_128 * (float)tid, &s, &c);
        rootI[tid] = make_float2(c, s);
    }
    const float2* Yp = g_Y + (size_t)blockIdx.x * 512;
    #pragma unroll
    for (int p = 0; p < 2; p++) {
        int i = tid + p * 256;
        ((float2*)Ys)[i] = Yp[i];
    }
    __syncthreads();

    // Phase A: Z[h,ky] = sum_kx Y[kx,ky] e^{+2pi i kx h/128}
    {
        int ky = tid & 15, hg = tid >> 4;   // thread handles h = hg + 16*j
        float zr[8], zi[8];
        int idx[8];
        #pragma unroll
        for (int j = 0; j < 8; j++) { zr[j] = 0.f; zi[j] = 0.f; idx[j] = 0; }

        // kx = 0..15
        for (int kxIdx = 0; kxIdx < 16; kxIdx++) {
            float2 y = Ys[kxIdx][ky];
            #pragma unroll
            for (int j = 0; j < 8; j++) {
                int h = hg + 16 * j;
                float2 e = rootI[idx[j]];
                zr[j] += y.x * e.x - y.y * e.y;
                zi[j] += y.x * e.y + y.y * e.x;
                idx[j] = (idx[j] + h) & 127;
            }
        }
        // kx = 112..127
        #pragma unroll
        for (int j = 0; j < 8; j++) idx[j] = (112 * (hg + 16 * j)) & 127;
        for (int kxIdx = 16; kxIdx < 32; kxIdx++) {
            float2 y = Ys[kxIdx][ky];
            #pragma unroll
            for (int j = 0; j < 8; j++) {
                int h = hg + 16 * j;
                float2 e = rootI[idx[j]];
                zr[j] += y.x * e.x - y.y * e.y;
                zi[j] += y.x * e.y + y.y * e.x;
                idx[j] = (idx[j] + h) & 127;
            }
        }
        #pragma unroll
        for (int j = 0; j < 8; j++) {
            int h = hg + 16 * j;
            ((float2*)&Zs4[h][0])[ky] = make_float2(zr[j], zi[j]);
        }
    }
    __syncthreads();

    // Phase B: thread -> (w, row-group). Twiddles live in registers;
    // Zs reads are warp-broadcast; output stores are coalesced along w.
    int w = tid & 127, rg = tid >> 7;
    float tc[16], ts[16];
    tc[0] = 1.f; ts[0] = 0.f;                 // DC: Re(Z0), not doubled
    #pragma unroll
    for (int k = 1; k < 16; k++) {
        float2 e = rootI[(k * w) & 127];
        tc[k] = 2.f * e.x;
        ts[k] = 2.f * e.y;
    }
    float* op = out + (size_t)blockIdx.x * 16384;
    for (int i = 0; i < 64; i++) {
        int r = rg * 64 + i;
        float acc = 0.f;
        #pragma unroll
        for (int k2 = 0; k2 < 8; k2++) {
            float4 z = Zs4[r][k2];   // (zr0, zi0, zr1, zi1)
            acc += z.x * tc[2 * k2]     - z.y * ts[2 * k2];
            acc += z.z * tc[2 * k2 + 1] - z.w * ts[2 * k2 + 1];
        }
        op[r * 128 + w] = acc;
    }
}

// ---------------------------------------------------------------------------
extern "C" void kernel_launch(void* const* d_in, const int* in_sizes, int n_in,
                              void* d_out, int out_size) {
    const float* X   = (const float*)d_in[0];
    const float* w0r = (const float*)d_in[1];
    const float* w0i = (const float*)d_in[2];
    const float* w1r = (const float*)d_in[3];
    const float* w1i = (const float*)d_in[4];
    float* out = (float*)d_out;

    k_forward<<<1024, 128>>>(X);
    k_modes<<<512, 256>>>(w0r, w0i, w1r, w1i);
    k_inverse<<<1024, 256>>>(out);
}